// round 10
// baseline (speedup 1.0000x reference)
#include <cuda_runtime.h>
#include <math.h>
#include <stdint.h>

// Shapes (fixed for this problem)
#define BB  1024   // batch
#define PP  256    // patches
#define DD  1024   // dino dim
#define DC  512    // clip dim

#define NSPLIT 4   // split-K factor for both GEMMs

// Scratch (no allocation allowed)
__device__ float g_tn  [BB * DD];          // normalized t
__device__ float g_vb  [BB * DD];          // normalized best patch per batch
__device__ float g_part[NSPLIT][BB * DD];  // split-K partial sums (reused)

__device__ __forceinline__ uint32_t f2tf32(float f) {
    uint32_t u;
    asm("cvt.rna.tf32.f32 %0, %1;" : "=r"(u) : "f"(f));
    return u;
}

#define MMA_TF32(acc, a, b) \
    asm volatile( \
        "mma.sync.aligned.m16n8k8.row.col.f32.tf32.tf32.f32 " \
        "{%0,%1,%2,%3}, {%4,%5,%6,%7}, {%8,%9}, {%0,%1,%2,%3};" \
        : "+f"((acc)[0]), "+f"((acc)[1]), "+f"((acc)[2]), "+f"((acc)[3]) \
        : "r"((a)[0]), "r"((a)[1]), "r"((a)[2]), "r"((a)[3]), \
          "r"((b)[0]), "r"((b)[1]))

// ===========================================================================
// Split-tf32 GEMM1 partial (fp32-equivalent accuracy), split-K over blockIdx.z.
// Cp[z][m,n] = sum_{k in slice z} A[m,k]*B[n,k]   (bias/tanh in reduce)
// BM=BN=64, BK=32, 128 threads, 2x2 warps, 32x32 warp tile.
// ===========================================================================
template<int K, int KS>     // KS = K per slice
__global__ void __launch_bounds__(128)
gemm_split_part(const float* __restrict__ A, const float* __restrict__ Bm,
                float* __restrict__ Cp)
{
    constexpr int PITCH = 68;            // hi at [0,32), lo at [32,64)
    constexpr int NKT   = KS / 32;

    __shared__ uint32_t As[64][PITCH];
    __shared__ uint32_t Bs[64][PITCH];

    const int tid  = threadIdx.x;
    const int lane = tid & 31;
    const int warp = tid >> 5;
    const int wm   = warp >> 1;
    const int wn   = warp & 1;
    const int gid  = lane >> 2;
    const int tig  = lane & 3;

    const int m0 = blockIdx.y * 64;
    const int n0 = blockIdx.x * 64;
    const int kbase = blockIdx.z * KS;
    float* __restrict__ C = Cp + (size_t)blockIdx.z * (BB * DD);

    const int lr = tid >> 3;
    const int lc = tid & 7;

    float c[2][4][4];
    #pragma unroll
    for (int i = 0; i < 2; i++)
        #pragma unroll
        for (int j = 0; j < 4; j++)
            #pragma unroll
            for (int q = 0; q < 4; q++) c[i][j][q] = 0.f;

    float4 pa[4], pb[4];

    auto load_tile = [&](int kk) {
        #pragma unroll
        for (int i = 0; i < 4; i++) {
            const int r = lr + i * 16;
            pa[i] = *(const float4*)(A  + (size_t)(m0 + r) * K + kk + lc * 4);
            pb[i] = *(const float4*)(Bm + (size_t)(n0 + r) * K + kk + lc * 4);
        }
    };
    auto store_tile = [&]() {
        #pragma unroll
        for (int i = 0; i < 4; i++) {
            const int r = lr + i * 16;
            uint4 ah = make_uint4(f2tf32(pa[i].x), f2tf32(pa[i].y),
                                  f2tf32(pa[i].z), f2tf32(pa[i].w));
            uint4 bh = make_uint4(f2tf32(pb[i].x), f2tf32(pb[i].y),
                                  f2tf32(pb[i].z), f2tf32(pb[i].w));
            uint4 al = make_uint4(f2tf32(pa[i].x - __uint_as_float(ah.x)),
                                  f2tf32(pa[i].y - __uint_as_float(ah.y)),
                                  f2tf32(pa[i].z - __uint_as_float(ah.z)),
                                  f2tf32(pa[i].w - __uint_as_float(ah.w)));
            uint4 bl = make_uint4(f2tf32(pb[i].x - __uint_as_float(bh.x)),
                                  f2tf32(pb[i].y - __uint_as_float(bh.y)),
                                  f2tf32(pb[i].z - __uint_as_float(bh.z)),
                                  f2tf32(pb[i].w - __uint_as_float(bh.w)));
            *(uint4*)&As[r][lc * 4]      = ah;
            *(uint4*)&As[r][32 + lc * 4] = al;
            *(uint4*)&Bs[r][lc * 4]      = bh;
            *(uint4*)&Bs[r][32 + lc * 4] = bl;
        }
    };

    load_tile(kbase);
    store_tile();
    __syncthreads();

    for (int kt = 0; kt < NKT; kt++) {
        if (kt + 1 < NKT) load_tile(kbase + (kt + 1) * 32);

        #pragma unroll
        for (int k8 = 0; k8 < 4; k8++) {
            const int k0 = k8 * 8;

            uint32_t af[2][4], afl[2][4];
            #pragma unroll
            for (int mi = 0; mi < 2; mi++) {
                const int row = wm * 32 + mi * 16 + gid;
                af[mi][0]  = As[row    ][k0 + tig];
                af[mi][1]  = As[row + 8][k0 + tig];
                af[mi][2]  = As[row    ][k0 + tig + 4];
                af[mi][3]  = As[row + 8][k0 + tig + 4];
                afl[mi][0] = As[row    ][32 + k0 + tig];
                afl[mi][1] = As[row + 8][32 + k0 + tig];
                afl[mi][2] = As[row    ][32 + k0 + tig + 4];
                afl[mi][3] = As[row + 8][32 + k0 + tig + 4];
            }
            uint32_t bf[4][2], bfl[4][2];
            #pragma unroll
            for (int nj = 0; nj < 4; nj++) {
                const int col = wn * 32 + nj * 8 + gid;
                bf[nj][0]  = Bs[col][k0 + tig];
                bf[nj][1]  = Bs[col][k0 + tig + 4];
                bfl[nj][0] = Bs[col][32 + k0 + tig];
                bfl[nj][1] = Bs[col][32 + k0 + tig + 4];
            }

            #pragma unroll
            for (int mi = 0; mi < 2; mi++)
                #pragma unroll
                for (int nj = 0; nj < 4; nj++) {
                    MMA_TF32(c[mi][nj], af[mi],  bf[nj]);    // hi*hi
                    MMA_TF32(c[mi][nj], af[mi],  bfl[nj]);   // hi*lo
                    MMA_TF32(c[mi][nj], afl[mi], bf[nj]);    // lo*hi
                }
        }

        if (kt + 1 < NKT) {
            __syncthreads();
            store_tile();
            __syncthreads();
        }
    }

    #pragma unroll
    for (int mi = 0; mi < 2; mi++) {
        const int row = m0 + wm * 32 + mi * 16 + gid;
        #pragma unroll
        for (int nj = 0; nj < 4; nj++) {
            const int col = n0 + wn * 32 + nj * 8 + tig * 2;
            *(float2*)(C + (size_t)row * DD + col) =
                make_float2(c[mi][nj][0], c[mi][nj][1]);
            *(float2*)(C + (size_t)(row + 8) * DD + col) =
                make_float2(c[mi][nj][2], c[mi][nj][3]);
        }
    }
}

// ===========================================================================
// GEMM2 partial: single-pass tf32, double-buffered, split-K over blockIdx.z.
// ===========================================================================
template<int K, int KS>
__global__ void __launch_bounds__(128)
gemm_db_part(const float* __restrict__ A, const float* __restrict__ Bm,
             float* __restrict__ Cp)
{
    constexpr int PITCH = 36;
    constexpr int NKT   = KS / 32;

    __shared__ uint32_t As[2][64][PITCH];
    __shared__ uint32_t Bs[2][64][PITCH];

    const int tid  = threadIdx.x;
    const int lane = tid & 31;
    const int warp = tid >> 5;
    const int wm   = warp >> 1;
    const int wn   = warp & 1;
    const int gid  = lane >> 2;
    const int tig  = lane & 3;

    const int m0 = blockIdx.y * 64;
    const int n0 = blockIdx.x * 64;
    const int kbase = blockIdx.z * KS;
    float* __restrict__ C = Cp + (size_t)blockIdx.z * (BB * DD);

    const int lr = tid >> 3;
    const int lc = tid & 7;

    float c[2][4][4];
    #pragma unroll
    for (int i = 0; i < 2; i++)
        #pragma unroll
        for (int j = 0; j < 4; j++)
            #pragma unroll
            for (int q = 0; q < 4; q++) c[i][j][q] = 0.f;

    float4 pa[4], pb[4];

    auto load_tile = [&](int kk) {
        #pragma unroll
        for (int i = 0; i < 4; i++) {
            const int r = lr + i * 16;
            pa[i] = *(const float4*)(A  + (size_t)(m0 + r) * K + kk + lc * 4);
            pb[i] = *(const float4*)(Bm + (size_t)(n0 + r) * K + kk + lc * 4);
        }
    };
    auto store_tile = [&](int buf) {
        #pragma unroll
        for (int i = 0; i < 4; i++) {
            const int r = lr + i * 16;
            *(uint4*)&As[buf][r][lc * 4] = make_uint4(f2tf32(pa[i].x), f2tf32(pa[i].y),
                                                      f2tf32(pa[i].z), f2tf32(pa[i].w));
            *(uint4*)&Bs[buf][r][lc * 4] = make_uint4(f2tf32(pb[i].x), f2tf32(pb[i].y),
                                                      f2tf32(pb[i].z), f2tf32(pb[i].w));
        }
    };

    load_tile(kbase);
    store_tile(0);
    __syncthreads();

    for (int kt = 0; kt < NKT; kt++) {
        const int buf = kt & 1;
        if (kt + 1 < NKT) load_tile(kbase + (kt + 1) * 32);

        #pragma unroll
        for (int k8 = 0; k8 < 4; k8++) {
            const int k0 = k8 * 8;

            uint32_t af[2][4];
            #pragma unroll
            for (int mi = 0; mi < 2; mi++) {
                const int row = wm * 32 + mi * 16 + gid;
                af[mi][0] = As[buf][row    ][k0 + tig];
                af[mi][1] = As[buf][row + 8][k0 + tig];
                af[mi][2] = As[buf][row    ][k0 + tig + 4];
                af[mi][3] = As[buf][row + 8][k0 + tig + 4];
            }
            uint32_t bf[4][2];
            #pragma unroll
            for (int nj = 0; nj < 4; nj++) {
                const int col = wn * 32 + nj * 8 + gid;
                bf[nj][0] = Bs[buf][col][k0 + tig];
                bf[nj][1] = Bs[buf][col][k0 + tig + 4];
            }

            #pragma unroll
            for (int mi = 0; mi < 2; mi++)
                #pragma unroll
                for (int nj = 0; nj < 4; nj++)
                    MMA_TF32(c[mi][nj], af[mi], bf[nj]);
        }

        if (kt + 1 < NKT) store_tile(buf ^ 1);
        __syncthreads();
    }

    #pragma unroll
    for (int mi = 0; mi < 2; mi++) {
        const int row = m0 + wm * 32 + mi * 16 + gid;
        #pragma unroll
        for (int nj = 0; nj < 4; nj++) {
            const int col = n0 + wn * 32 + nj * 8 + tig * 2;
            *(float2*)(C + (size_t)row * DD + col) =
                make_float2(c[mi][nj][0], c[mi][nj][1]);
            *(float2*)(C + (size_t)(row + 8) * DD + col) =
                make_float2(c[mi][nj][2], c[mi][nj][3]);
        }
    }
}

// ---------------------------------------------------------------------------
// Fused: t = tanh(sum_z p[z] + bias); tn = t / max(||t||, 1e-12). 1 blk/row.
// ---------------------------------------------------------------------------
__global__ void __launch_bounds__(256)
reduce_tanh_norm_kernel(const float* __restrict__ parts,
                        const float* __restrict__ bias, float* __restrict__ out)
{
    const int b = blockIdx.x;
    const int t = threadIdx.x;
    const int lane = t & 31, warp = t >> 5;

    float4 s  = ((const float4*)(parts + (size_t)b * DD))[t];
    #pragma unroll
    for (int z = 1; z < NSPLIT; z++) {
        float4 a = ((const float4*)(parts + (size_t)z * (BB * DD) + (size_t)b * DD))[t];
        s.x += a.x; s.y += a.y; s.z += a.z; s.w += a.w;
    }
    float4 bb = ((const float4*)bias)[t];
    float4 v;
    v.x = tanhf(s.x + bb.x);
    v.y = tanhf(s.y + bb.y);
    v.z = tanhf(s.z + bb.z);
    v.w = tanhf(s.w + bb.w);

    float ss = v.x*v.x + v.y*v.y + v.z*v.z + v.w*v.w;
    #pragma unroll
    for (int o = 16; o; o >>= 1) ss += __shfl_xor_sync(0xffffffffu, ss, o);

    __shared__ float sred[8];
    __shared__ float sinv;
    if (lane == 0) sred[warp] = ss;
    __syncthreads();
    if (t == 0) {
        float tot = 0.f;
        #pragma unroll
        for (int w = 0; w < 8; w++) tot += sred[w];
        sinv = 1.0f / fmaxf(sqrtf(tot), 1e-12f);
    }
    __syncthreads();
    const float inv = sinv;
    v.x *= inv; v.y *= inv; v.z *= inv; v.w *= inv;
    ((float4*)(out + (size_t)b * DD))[t] = v;
}

// ---------------------------------------------------------------------------
// out = sum_z p[z] (vectorized, fixed order => deterministic)
// ---------------------------------------------------------------------------
__global__ void __launch_bounds__(256)
reduce_add_kernel(const float* __restrict__ parts, float* __restrict__ out)
{
    const int i = blockIdx.x * 256 + threadIdx.x;
    float4 s = ((const float4*)parts)[i];
    #pragma unroll
    for (int z = 1; z < NSPLIT; z++) {
        float4 a = ((const float4*)(parts + (size_t)z * (BB * DD)))[i];
        s.x += a.x; s.y += a.y; s.z += a.z; s.w += a.w;
    }
    ((float4*)out)[i] = s;
}

// ---------------------------------------------------------------------------
// sims + argmax + gather (HBM-bound; reads 1 GB once)
// ---------------------------------------------------------------------------
__global__ void __launch_bounds__(256)
sims_argmax_kernel(const float* __restrict__ visual,
                   const float* __restrict__ tn,
                   float* __restrict__ vb)
{
    const int b = blockIdx.x;
    const int lane = threadIdx.x & 31;
    const int warp = threadIdx.x >> 5;

    const float4* v4 = (const float4*)(visual + (size_t)b * PP * DD);
    const float4* t4 = (const float4*)(tn + (size_t)b * DD);

    float4 tr[8];
    #pragma unroll
    for (int k = 0; k < 8; k++) tr[k] = t4[lane + 32 * k];

    float best = -1e30f; int bidx = 0; float bss = 1.f;

    #pragma unroll 2
    for (int pp = 0; pp < 32; pp++) {
        const int p = warp * 32 + pp;
        const float4* row = v4 + (size_t)p * (DD / 4);
        float dot = 0.f, ss = 0.f;
        #pragma unroll
        for (int k = 0; k < 8; k++) {
            float4 v = row[lane + 32 * k];
            dot += v.x * tr[k].x + v.y * tr[k].y + v.z * tr[k].z + v.w * tr[k].w;
            ss  += v.x * v.x + v.y * v.y + v.z * v.z + v.w * v.w;
        }
        #pragma unroll
        for (int o = 16; o; o >>= 1) {
            dot += __shfl_xor_sync(0xffffffffu, dot, o);
            ss  += __shfl_xor_sync(0xffffffffu, ss,  o);
        }
        const float sim = dot / fmaxf(sqrtf(ss), 1e-12f);
        if (sim > best) { best = sim; bidx = p; bss = ss; }
    }

    __shared__ float sval[8]; __shared__ int sidx[8]; __shared__ float ssum[8];
    __shared__ int s_p; __shared__ float s_inv;
    if (lane == 0) { sval[warp] = best; sidx[warp] = bidx; ssum[warp] = bss; }
    __syncthreads();
    if (threadIdx.x == 0) {
        float bv = sval[0]; int bi = sidx[0]; float bs = ssum[0];
        #pragma unroll
        for (int w = 1; w < 8; w++) {
            if (sval[w] > bv || (sval[w] == bv && sidx[w] < bi)) {
                bv = sval[w]; bi = sidx[w]; bs = ssum[w];
            }
        }
        s_p = bi;
        s_inv = 1.0f / fmaxf(sqrtf(bs), 1e-12f);
    }
    __syncthreads();

    const int p = s_p;
    const float inv = s_inv;
    const float4* row = v4 + (size_t)p * (DD / 4);
    float4* ob = (float4*)(vb + (size_t)b * DD);
    for (int i = threadIdx.x; i < DD / 4; i += 256) {
        float4 v = row[i];
        v.x *= inv; v.y *= inv; v.z *= inv; v.w *= inv;
        ob[i] = v;
    }
}

// ---------------------------------------------------------------------------
extern "C" void kernel_launch(void* const* d_in, const int* in_sizes, int n_in,
                              void* d_out, int out_size)
{
    const float* visual = (const float*)d_in[0];   // [1024, 256, 1024]
    const float* text   = (const float*)d_in[1];   // [1024, 512]
    const float* W      = (const float*)d_in[2];   // [1024, 512]
    const float* bias   = (const float*)d_in[3];   // [1024]
    float* out = (float*)d_out;                    // [1024, 1024]

    float *p_tn, *p_vb, *p_part;
    cudaGetSymbolAddress((void**)&p_tn,   g_tn);
    cudaGetSymbolAddress((void**)&p_vb,   g_vb);
    cudaGetSymbolAddress((void**)&p_part, g_part);

    // 1) partials of text @ W^T  (split-tf32, split-K=4)
    gemm_split_part<DC, DC/NSPLIT><<<dim3(16, 16, NSPLIT), 128>>>(text, W, p_part);
    // 2) tn = l2norm(tanh(sum parts + bias))   (fused reduce)
    reduce_tanh_norm_kernel<<<BB, 256>>>(p_part, bias, p_tn);
    // 3) per-b argmax over patches + gather normalized best patch
    sims_argmax_kernel<<<BB, 256>>>(visual, p_tn, p_vb);
    // 4) partials of tn @ vb^T  (single-pass tf32, split-K=4)
    gemm_db_part<DD, DD/NSPLIT><<<dim3(16, 16, NSPLIT), 128>>>(p_tn, p_vb, p_part);
    // 5) out = sum parts
    reduce_add_kernel<<<BB * DD / 4 / 256, 256>>>(p_part, out);
}

// round 11
// speedup vs baseline: 1.0066x; 1.0066x over previous
#include <cuda_runtime.h>
#include <math.h>
#include <stdint.h>

// Shapes (fixed for this problem)
#define BB  1024   // batch
#define PP  256    // patches
#define DD  1024   // dino dim
#define DC  512    // clip dim

#define NSPLIT 4   // split-K factor for both GEMMs

// Scratch (no allocation allowed)
__device__ float g_tn  [BB * DD];          // normalized t
__device__ float g_vb  [BB * DD];          // normalized best patch per batch
__device__ float g_part[NSPLIT][BB * DD];  // split-K partial sums (reused)

__device__ __forceinline__ uint32_t f2tf32(float f) {
    uint32_t u;
    asm("cvt.rna.tf32.f32 %0, %1;" : "=r"(u) : "f"(f));
    return u;
}
__device__ __forceinline__ uint32_t smem_u32(const void* p) {
    uint32_t r;
    asm("{ .reg .u64 t; cvta.to.shared.u64 t, %1; cvt.u32.u64 %0, t; }"
        : "=r"(r) : "l"(p));
    return r;
}

#define MMA_TF32(acc, a, b) \
    asm volatile( \
        "mma.sync.aligned.m16n8k8.row.col.f32.tf32.tf32.f32 " \
        "{%0,%1,%2,%3}, {%4,%5,%6,%7}, {%8,%9}, {%0,%1,%2,%3};" \
        : "+f"((acc)[0]), "+f"((acc)[1]), "+f"((acc)[2]), "+f"((acc)[3]) \
        : "r"((a)[0]), "r"((a)[1]), "r"((a)[2]), "r"((a)[3]), \
          "r"((b)[0]), "r"((b)[1]))

// 4x m8n8 b16 ldmatrix: over a 16-row x 8-b32-col tile this yields the exact
// m16n8k8 tf32 fragment set (each 32-bit reg = one b32 element).
#define LDSM4(r0, r1, r2, r3, addr) \
    asm volatile("ldmatrix.sync.aligned.m8n8.x4.shared.b16 {%0,%1,%2,%3}, [%4];" \
        : "=r"(r0), "=r"(r1), "=r"(r2), "=r"(r3) : "r"(addr))

// ===========================================================================
// Split-tf32 GEMM1 partial (fp32-equivalent accuracy), split-K over blockIdx.z.
// Cp[z][m,n] = sum_{k in slice z} A[m,k]*B[n,k]   (bias/tanh in reduce)
// BM=BN=64, BK=32, 128 threads, 2x2 warps, 32x32 warp tile. LDSM fragments.
// ===========================================================================
template<int K, int KS>     // KS = K per slice
__global__ void __launch_bounds__(128)
gemm_split_part(const float* __restrict__ A, const float* __restrict__ Bm,
                float* __restrict__ Cp)
{
    constexpr int PITCH = 68;            // hi at [0,32), lo at [32,64)
    constexpr int NKT   = KS / 32;

    __shared__ __align__(16) uint32_t As[64][PITCH];
    __shared__ __align__(16) uint32_t Bs[64][PITCH];

    const int tid  = threadIdx.x;
    const int lane = tid & 31;
    const int warp = tid >> 5;
    const int wm   = warp >> 1;
    const int wn   = warp & 1;

    const int m0 = blockIdx.y * 64;
    const int n0 = blockIdx.x * 64;
    const int kbase = blockIdx.z * KS;
    float* __restrict__ C = Cp + (size_t)blockIdx.z * (BB * DD);

    const int lr = tid >> 3;
    const int lc = tid & 7;

    // LDSM row-pointer mapping: q = lane>>3 selects (row-half, col-half)
    const int q  = lane >> 3;
    const int jj = lane & 7;
    const int frow = jj + 8 * (q & 1);      // row within 16-row tile
    const int fcol = 4 * (q >> 1);          // b32 col offset (0 or 4)

    const uint32_t aBase = smem_u32(&As[0][0]);
    const uint32_t bBase = smem_u32(&Bs[0][0]);
    // byte addresses of k8=0, hi fragments
    const uint32_t aAddr = aBase + ((wm * 32 + frow) * PITCH + fcol) * 4;
    const uint32_t bAddr = bBase + ((wn * 32 + frow) * PITCH + fcol) * 4;
    constexpr uint32_t TILE16 = 16u * PITCH * 4;   // 16-row stride (bytes)
    constexpr uint32_t LOOFF  = 32u * 4;           // lo half at +32 words

    float c[2][4][4];
    #pragma unroll
    for (int i = 0; i < 2; i++)
        #pragma unroll
        for (int j = 0; j < 4; j++)
            #pragma unroll
            for (int qq = 0; qq < 4; qq++) c[i][j][qq] = 0.f;

    float4 pa[4], pb[4];

    auto load_tile = [&](int kk) {
        #pragma unroll
        for (int i = 0; i < 4; i++) {
            const int r = lr + i * 16;
            pa[i] = *(const float4*)(A  + (size_t)(m0 + r) * K + kk + lc * 4);
            pb[i] = *(const float4*)(Bm + (size_t)(n0 + r) * K + kk + lc * 4);
        }
    };
    auto store_tile = [&]() {
        #pragma unroll
        for (int i = 0; i < 4; i++) {
            const int r = lr + i * 16;
            uint4 ah = make_uint4(f2tf32(pa[i].x), f2tf32(pa[i].y),
                                  f2tf32(pa[i].z), f2tf32(pa[i].w));
            uint4 bh = make_uint4(f2tf32(pb[i].x), f2tf32(pb[i].y),
                                  f2tf32(pb[i].z), f2tf32(pb[i].w));
            uint4 al = make_uint4(f2tf32(pa[i].x - __uint_as_float(ah.x)),
                                  f2tf32(pa[i].y - __uint_as_float(ah.y)),
                                  f2tf32(pa[i].z - __uint_as_float(ah.z)),
                                  f2tf32(pa[i].w - __uint_as_float(ah.w)));
            uint4 bl = make_uint4(f2tf32(pb[i].x - __uint_as_float(bh.x)),
                                  f2tf32(pb[i].y - __uint_as_float(bh.y)),
                                  f2tf32(pb[i].z - __uint_as_float(bh.z)),
                                  f2tf32(pb[i].w - __uint_as_float(bh.w)));
            *(uint4*)&As[r][lc * 4]      = ah;
            *(uint4*)&As[r][32 + lc * 4] = al;
            *(uint4*)&Bs[r][lc * 4]      = bh;
            *(uint4*)&Bs[r][32 + lc * 4] = bl;
        }
    };

    load_tile(kbase);
    store_tile();
    __syncthreads();

    for (int kt = 0; kt < NKT; kt++) {
        if (kt + 1 < NKT) load_tile(kbase + (kt + 1) * 32);

        #pragma unroll
        for (int k8 = 0; k8 < 4; k8++) {
            const uint32_t ko = (uint32_t)k8 * 32;   // 8 b32 cols = 32 bytes

            uint32_t af[2][4], afl[2][4];
            LDSM4(af[0][0],  af[0][1],  af[0][2],  af[0][3],  aAddr + ko);
            LDSM4(af[1][0],  af[1][1],  af[1][2],  af[1][3],  aAddr + TILE16 + ko);
            LDSM4(afl[0][0], afl[0][1], afl[0][2], afl[0][3], aAddr + LOOFF + ko);
            LDSM4(afl[1][0], afl[1][1], afl[1][2], afl[1][3], aAddr + TILE16 + LOOFF + ko);

            // B: x4 over 16 rows covers two n-tiles: regs = (b[nj][0], b[nj+1][0],
            //                                               b[nj][1], b[nj+1][1])
            uint32_t bf[4][2], bfl[4][2];
            LDSM4(bf[0][0],  bf[1][0],  bf[0][1],  bf[1][1],  bAddr + ko);
            LDSM4(bf[2][0],  bf[3][0],  bf[2][1],  bf[3][1],  bAddr + TILE16 + ko);
            LDSM4(bfl[0][0], bfl[1][0], bfl[0][1], bfl[1][1], bAddr + LOOFF + ko);
            LDSM4(bfl[2][0], bfl[3][0], bfl[2][1], bfl[3][1], bAddr + TILE16 + LOOFF + ko);

            #pragma unroll
            for (int mi = 0; mi < 2; mi++)
                #pragma unroll
                for (int nj = 0; nj < 4; nj++) {
                    MMA_TF32(c[mi][nj], af[mi],  bf[nj]);    // hi*hi
                    MMA_TF32(c[mi][nj], af[mi],  bfl[nj]);   // hi*lo
                    MMA_TF32(c[mi][nj], afl[mi], bf[nj]);    // lo*hi
                }
        }

        if (kt + 1 < NKT) {
            __syncthreads();
            store_tile();
            __syncthreads();
        }
    }

    const int gid = lane >> 2;
    const int tig = lane & 3;
    #pragma unroll
    for (int mi = 0; mi < 2; mi++) {
        const int row = m0 + wm * 32 + mi * 16 + gid;
        #pragma unroll
        for (int nj = 0; nj < 4; nj++) {
            const int col = n0 + wn * 32 + nj * 8 + tig * 2;
            *(float2*)(C + (size_t)row * DD + col) =
                make_float2(c[mi][nj][0], c[mi][nj][1]);
            *(float2*)(C + (size_t)(row + 8) * DD + col) =
                make_float2(c[mi][nj][2], c[mi][nj][3]);
        }
    }
}

// ===========================================================================
// GEMM2 partial: single-pass tf32, double-buffered, split-K, LDSM fragments.
// ===========================================================================
template<int K, int KS>
__global__ void __launch_bounds__(128)
gemm_db_part(const float* __restrict__ A, const float* __restrict__ Bm,
             float* __restrict__ Cp)
{
    constexpr int PITCH = 36;
    constexpr int NKT   = KS / 32;

    __shared__ __align__(16) uint32_t As[2][64][PITCH];
    __shared__ __align__(16) uint32_t Bs[2][64][PITCH];

    const int tid  = threadIdx.x;
    const int lane = tid & 31;
    const int warp = tid >> 5;
    const int wm   = warp >> 1;
    const int wn   = warp & 1;

    const int m0 = blockIdx.y * 64;
    const int n0 = blockIdx.x * 64;
    const int kbase = blockIdx.z * KS;
    float* __restrict__ C = Cp + (size_t)blockIdx.z * (BB * DD);

    const int lr = tid >> 3;
    const int lc = tid & 7;

    const int q  = lane >> 3;
    const int jj = lane & 7;
    const int frow = jj + 8 * (q & 1);
    const int fcol = 4 * (q >> 1);

    const uint32_t aBase = smem_u32(&As[0][0][0]);
    const uint32_t bBase = smem_u32(&Bs[0][0][0]);
    const uint32_t aAddr = aBase + ((wm * 32 + frow) * PITCH + fcol) * 4;
    const uint32_t bAddr = bBase + ((wn * 32 + frow) * PITCH + fcol) * 4;
    constexpr uint32_t TILE16  = 16u * PITCH * 4;     // 16-row stride
    constexpr uint32_t BUFSTR  = 64u * PITCH * 4;     // buffer stride

    float c[2][4][4];
    #pragma unroll
    for (int i = 0; i < 2; i++)
        #pragma unroll
        for (int j = 0; j < 4; j++)
            #pragma unroll
            for (int qq = 0; qq < 4; qq++) c[i][j][qq] = 0.f;

    float4 pa[4], pb[4];

    auto load_tile = [&](int kk) {
        #pragma unroll
        for (int i = 0; i < 4; i++) {
            const int r = lr + i * 16;
            pa[i] = *(const float4*)(A  + (size_t)(m0 + r) * K + kk + lc * 4);
            pb[i] = *(const float4*)(Bm + (size_t)(n0 + r) * K + kk + lc * 4);
        }
    };
    auto store_tile = [&](int buf) {
        #pragma unroll
        for (int i = 0; i < 4; i++) {
            const int r = lr + i * 16;
            *(uint4*)&As[buf][r][lc * 4] = make_uint4(f2tf32(pa[i].x), f2tf32(pa[i].y),
                                                      f2tf32(pa[i].z), f2tf32(pa[i].w));
            *(uint4*)&Bs[buf][r][lc * 4] = make_uint4(f2tf32(pb[i].x), f2tf32(pb[i].y),
                                                      f2tf32(pb[i].z), f2tf32(pb[i].w));
        }
    };

    load_tile(kbase);
    store_tile(0);
    __syncthreads();

    for (int kt = 0; kt < NKT; kt++) {
        const uint32_t boff = (uint32_t)(kt & 1) * BUFSTR;
        if (kt + 1 < NKT) load_tile(kbase + (kt + 1) * 32);

        #pragma unroll
        for (int k8 = 0; k8 < 4; k8++) {
            const uint32_t ko = boff + (uint32_t)k8 * 32;

            uint32_t af[2][4];
            LDSM4(af[0][0], af[0][1], af[0][2], af[0][3], aAddr + ko);
            LDSM4(af[1][0], af[1][1], af[1][2], af[1][3], aAddr + TILE16 + ko);

            uint32_t bf[4][2];
            LDSM4(bf[0][0], bf[1][0], bf[0][1], bf[1][1], bAddr + ko);
            LDSM4(bf[2][0], bf[3][0], bf[2][1], bf[3][1], bAddr + TILE16 + ko);

            #pragma unroll
            for (int mi = 0; mi < 2; mi++)
                #pragma unroll
                for (int nj = 0; nj < 4; nj++)
                    MMA_TF32(c[mi][nj], af[mi], bf[nj]);
        }

        if (kt + 1 < NKT) store_tile((kt & 1) ^ 1);
        __syncthreads();
    }

    const int gid = lane >> 2;
    const int tig = lane & 3;
    #pragma unroll
    for (int mi = 0; mi < 2; mi++) {
        const int row = m0 + wm * 32 + mi * 16 + gid;
        #pragma unroll
        for (int nj = 0; nj < 4; nj++) {
            const int col = n0 + wn * 32 + nj * 8 + tig * 2;
            *(float2*)(C + (size_t)row * DD + col) =
                make_float2(c[mi][nj][0], c[mi][nj][1]);
            *(float2*)(C + (size_t)(row + 8) * DD + col) =
                make_float2(c[mi][nj][2], c[mi][nj][3]);
        }
    }
}

// ---------------------------------------------------------------------------
// Fused: t = tanh(sum_z p[z] + bias); tn = t / max(||t||, 1e-12). 1 blk/row.
// ---------------------------------------------------------------------------
__global__ void __launch_bounds__(256)
reduce_tanh_norm_kernel(const float* __restrict__ parts,
                        const float* __restrict__ bias, float* __restrict__ out)
{
    const int b = blockIdx.x;
    const int t = threadIdx.x;
    const int lane = t & 31, warp = t >> 5;

    float4 s  = ((const float4*)(parts + (size_t)b * DD))[t];
    #pragma unroll
    for (int z = 1; z < NSPLIT; z++) {
        float4 a = ((const float4*)(parts + (size_t)z * (BB * DD) + (size_t)b * DD))[t];
        s.x += a.x; s.y += a.y; s.z += a.z; s.w += a.w;
    }
    float4 bb = ((const float4*)bias)[t];
    float4 v;
    v.x = tanhf(s.x + bb.x);
    v.y = tanhf(s.y + bb.y);
    v.z = tanhf(s.z + bb.z);
    v.w = tanhf(s.w + bb.w);

    float ss = v.x*v.x + v.y*v.y + v.z*v.z + v.w*v.w;
    #pragma unroll
    for (int o = 16; o; o >>= 1) ss += __shfl_xor_sync(0xffffffffu, ss, o);

    __shared__ float sred[8];
    __shared__ float sinv;
    if (lane == 0) sred[warp] = ss;
    __syncthreads();
    if (t == 0) {
        float tot = 0.f;
        #pragma unroll
        for (int w = 0; w < 8; w++) tot += sred[w];
        sinv = 1.0f / fmaxf(sqrtf(tot), 1e-12f);
    }
    __syncthreads();
    const float inv = sinv;
    v.x *= inv; v.y *= inv; v.z *= inv; v.w *= inv;
    ((float4*)(out + (size_t)b * DD))[t] = v;
}

// ---------------------------------------------------------------------------
// out = sum_z p[z] (vectorized, fixed order => deterministic)
// ---------------------------------------------------------------------------
__global__ void __launch_bounds__(256)
reduce_add_kernel(const float* __restrict__ parts, float* __restrict__ out)
{
    const int i = blockIdx.x * 256 + threadIdx.x;
    float4 s = ((const float4*)parts)[i];
    #pragma unroll
    for (int z = 1; z < NSPLIT; z++) {
        float4 a = ((const float4*)(parts + (size_t)z * (BB * DD)))[i];
        s.x += a.x; s.y += a.y; s.z += a.z; s.w += a.w;
    }
    ((float4*)out)[i] = s;
}

// ---------------------------------------------------------------------------
// sims + argmax + gather (HBM-bound; reads 1 GB once)
// ---------------------------------------------------------------------------
__global__ void __launch_bounds__(256)
sims_argmax_kernel(const float* __restrict__ visual,
                   const float* __restrict__ tn,
                   float* __restrict__ vb)
{
    const int b = blockIdx.x;
    const int lane = threadIdx.x & 31;
    const int warp = threadIdx.x >> 5;

    const float4* v4 = (const float4*)(visual + (size_t)b * PP * DD);
    const float4* t4 = (const float4*)(tn + (size_t)b * DD);

    float4 tr[8];
    #pragma unroll
    for (int k = 0; k < 8; k++) tr[k] = t4[lane + 32 * k];

    float best = -1e30f; int bidx = 0; float bss = 1.f;

    #pragma unroll 2
    for (int pp = 0; pp < 32; pp++) {
        const int p = warp * 32 + pp;
        const float4* row = v4 + (size_t)p * (DD / 4);
        float dot = 0.f, ss = 0.f;
        #pragma unroll
        for (int k = 0; k < 8; k++) {
            float4 v = row[lane + 32 * k];
            dot += v.x * tr[k].x + v.y * tr[k].y + v.z * tr[k].z + v.w * tr[k].w;
            ss  += v.x * v.x + v.y * v.y + v.z * v.z + v.w * v.w;
        }
        #pragma unroll
        for (int o = 16; o; o >>= 1) {
            dot += __shfl_xor_sync(0xffffffffu, dot, o);
            ss  += __shfl_xor_sync(0xffffffffu, ss,  o);
        }
        const float sim = dot / fmaxf(sqrtf(ss), 1e-12f);
        if (sim > best) { best = sim; bidx = p; bss = ss; }
    }

    __shared__ float sval[8]; __shared__ int sidx[8]; __shared__ float ssum[8];
    __shared__ int s_p; __shared__ float s_inv;
    if (lane == 0) { sval[warp] = best; sidx[warp] = bidx; ssum[warp] = bss; }
    __syncthreads();
    if (threadIdx.x == 0) {
        float bv = sval[0]; int bi = sidx[0]; float bs = ssum[0];
        #pragma unroll
        for (int w = 1; w < 8; w++) {
            if (sval[w] > bv || (sval[w] == bv && sidx[w] < bi)) {
                bv = sval[w]; bi = sidx[w]; bs = ssum[w];
            }
        }
        s_p = bi;
        s_inv = 1.0f / fmaxf(sqrtf(bs), 1e-12f);
    }
    __syncthreads();

    const int p = s_p;
    const float inv = s_inv;
    const float4* row = v4 + (size_t)p * (DD / 4);
    float4* ob = (float4*)(vb + (size_t)b * DD);
    for (int i = threadIdx.x; i < DD / 4; i += 256) {
        float4 v = row[i];
        v.x *= inv; v.y *= inv; v.z *= inv; v.w *= inv;
        ob[i] = v;
    }
}

// ---------------------------------------------------------------------------
extern "C" void kernel_launch(void* const* d_in, const int* in_sizes, int n_in,
                              void* d_out, int out_size)
{
    const float* visual = (const float*)d_in[0];   // [1024, 256, 1024]
    const float* text   = (const float*)d_in[1];   // [1024, 512]
    const float* W      = (const float*)d_in[2];   // [1024, 512]
    const float* bias   = (const float*)d_in[3];   // [1024]
    float* out = (float*)d_out;                    // [1024, 1024]

    float *p_tn, *p_vb, *p_part;
    cudaGetSymbolAddress((void**)&p_tn,   g_tn);
    cudaGetSymbolAddress((void**)&p_vb,   g_vb);
    cudaGetSymbolAddress((void**)&p_part, g_part);

    // 1) partials of text @ W^T  (split-tf32, split-K=4)
    gemm_split_part<DC, DC/NSPLIT><<<dim3(16, 16, NSPLIT), 128>>>(text, W, p_part);
    // 2) tn = l2norm(tanh(sum parts + bias))   (fused reduce)
    reduce_tanh_norm_kernel<<<BB, 256>>>(p_part, bias, p_tn);
    // 3) per-b argmax over patches + gather normalized best patch
    sims_argmax_kernel<<<BB, 256>>>(visual, p_tn, p_vb);
    // 4) partials of tn @ vb^T  (single-pass tf32, split-K=4)
    gemm_db_part<DD, DD/NSPLIT><<<dim3(16, 16, NSPLIT), 128>>>(p_tn, p_vb, p_part);
    // 5) out = sum parts
    reduce_add_kernel<<<BB * DD / 4 / 256, 256>>>(p_part, out);
}